// round 14
// baseline (speedup 1.0000x reference)
#include <cuda_runtime.h>

// BoxBlur 13x13 reflect, (8,64,512,512) fp32. Separable, sliding-window.
// R12 internals + software pipelining: CTA owns 4 chunks (64 rows); per chunk,
// the NEXT chunk's 28 input rows are loaded into regs (MLP=28/thread) BEFORE
// the current chunk's smem-bound pass2+flush, hiding DRAM latency inside the
// warp. Ring-free vertical accumulate from regs kills the outgoing reload
// (LDG/out 2.75 -> 1.75). Double-buffered vs, ONE sync per chunk.
// occ 2 (64-reg budget) so v[28] stays in registers.

#define Wd 512
#define Hd 512
#define TY 16
#define NCH 4             // chunks per CTA -> 64 rows
#define NT 512
#define PW 513            // vs stride (conflict-free)
#define OW 513            // os stride (conflict-free)
#define KHALF 6
#define RAWH (TY + 12)    // 28 rows loaded per chunk

#define SMEM_FLOATS (2 * TY * PW + TY * OW)
#define SMEM_BYTES  (SMEM_FLOATS * 4)       // 98,496 B -> 2 CTAs/SM

__device__ __forceinline__ int reflect_i(int i, int n) {
    // jnp.pad 'reflect', pad (6) < n: single fold.
    if (i < 0) i = -i;
    if (i >= n) i = 2 * n - 2 - i;
    return i;
}

// Load 28 rows (y0-6 .. y0+21) of column t into regs: 28 independent LDGs.
__device__ __forceinline__ void load28(float v[RAWH], const float* __restrict__ ip,
                                       int y0, int t) {
    #pragma unroll
    for (int jj = 0; jj < RAWH; jj++)
        v[jj] = ip[reflect_i(y0 + jj - KHALF, Hd) * Wd + t];
}

// Fold v[] into vertical running 13-sums; store 16 rows to vs.
__device__ __forceinline__ void accum_store(const float v[RAWH],
                                            float* __restrict__ vsb, int t) {
    float s = 0.0f;
    #pragma unroll
    for (int jj = 0; jj < RAWH; jj++) {
        s += v[jj];
        if (jj >= 12) {
            vsb[(jj - 12) * PW + t] = s;
            s -= v[jj - 12];
        }
    }
}

// R12's warp-private horizontal pass + flush (verbatim).
__device__ __forceinline__ void pass2_flush(const float* __restrict__ vsb,
                                            float* __restrict__ os,
                                            float* __restrict__ op,
                                            int y0, int t, float k0) {
    const int lane = t & 31;
    const int w    = t >> 5;        // warp 0..15: columns [32w, 32w+32)
    const int rl   = lane & 15;     // row 0..15
    const int sc   = lane >> 4;     // half-block select
    const int xb   = 32 * w + 16 * sc;
    const float* __restrict__ vrow = vsb + rl * PW;
    float* __restrict__ orow = os + rl * OW;

    float s = 0.0f;
    #pragma unroll
    for (int k = 0; k < 13; k++)
        s += vrow[reflect_i(xb - KHALF + k, Wd)];
    #pragma unroll
    for (int i = 0; i < 16; i++) {
        orow[xb + i] = s * k0;      // STS banks (rl+16sc+i)%32: conflict-free
        s += vrow[reflect_i(xb + i + KHALF + 1, Wd)]
           - vrow[reflect_i(xb + i - KHALF, Wd)];
    }
    __syncwarp();

    // flush own 32-col block: lane = column -> 128B coalesced STG per row
    const int c = 32 * w + lane;
    #pragma unroll
    for (int row = 0; row < TY; row++)
        op[(size_t)(y0 + row) * Wd + c] = os[row * OW + c];
}

__global__ __launch_bounds__(NT, 2)
void boxblur14(const float* __restrict__ in,
               const float* __restrict__ kern,
               float* __restrict__ out) {
    extern __shared__ float sm[];
    float* __restrict__ vsA = sm;                 // [TY][PW]
    float* __restrict__ vsB = sm + TY * PW;       // [TY][PW]
    float* __restrict__ os  = sm + 2 * TY * PW;   // [TY][OW] warp-private slices

    const int ybase = blockIdx.x * (TY * NCH);
    const int plane = blockIdx.y;
    const float* __restrict__ ip = in  + (size_t)plane * (Hd * Wd);
    float*       __restrict__ op = out + (size_t)plane * (Hd * Wd);
    const int t = threadIdx.x;                    // 0..511
    const float k0 = kern[0];                     // 1/169

    float v[RAWH];

    // prologue: chunk 0 vertical sums
    load28(v, ip, ybase, t);
    accum_store(v, vsA, t);
    __syncthreads();

    #pragma unroll 1
    for (int c = 0; c < NCH; c++) {
        float* __restrict__ vcur = (c & 1) ? vsB : vsA;
        float* __restrict__ vnxt = (c & 1) ? vsA : vsB;

        if (c + 1 < NCH)
            load28(v, ip, ybase + (c + 1) * TY, t);   // 28 LDGs in flight...
        pass2_flush(vcur, os, op, ybase + c * TY, t, k0);  // ...hidden by smem work
        if (c + 1 < NCH)
            accum_store(v, vnxt, t);
        __syncthreads();   // vs_next ready; also WAR cover for buffer reuse
    }
}

extern "C" void kernel_launch(void* const* d_in, const int* in_sizes, int n_in,
                              void* d_out, int out_size) {
    const float* input  = (const float*)d_in[0];   // (8,64,512,512) fp32
    const float* kernel = (const float*)d_in[1];   // (1,13,13) fp32 uniform
    float* out = (float*)d_out;

    cudaFuncSetAttribute(boxblur14, cudaFuncAttributeMaxDynamicSharedMemorySize,
                         SMEM_BYTES);

    dim3 grid(Hd / (TY * NCH), 8 * 64);    // (8 stripes, 512 planes) = 4096 CTAs
    boxblur14<<<grid, NT, SMEM_BYTES>>>(input, kernel, out);
}

// round 15
// speedup vs baseline: 1.1221x; 1.1221x over previous
#include <cuda_runtime.h>

// BoxBlur 13x13 reflect, (8,64,512,512) fp32. Separable, sliding-window.
// = R12 winner (186.7us, DRAM 70.7%) with 3 micro-opts, structure untouched:
//   1. interior-CTA fast path in pass 1 (no reflect ALU, pointer walk)
//   2. interior-warp fast path in pass 2 (immediate-offset LDS)
//   3. __stcs streaming stores (output never re-read; keep L2 for read halos)

#define Wd 512
#define Hd 512
#define TY 16
#define NT 512
#define PW 513            // vs stride (conflict-free) — load-bearing, do not change
#define OW 513            // os stride (conflict-free)
#define KHALF 6

#define SMEM_FLOATS (TY * PW + TY * OW)
#define SMEM_BYTES  (SMEM_FLOATS * 4)       // 65,664 B -> 3 CTAs/SM (197KB)

__device__ __forceinline__ int reflect_i(int i, int n) {
    // jnp.pad 'reflect', pad (6) < n: single fold.
    if (i < 0) i = -i;
    if (i >= n) i = 2 * n - 2 - i;
    return i;
}

__global__ __launch_bounds__(NT, 3)
void boxblur15(const float* __restrict__ in,
               const float* __restrict__ kern,
               float* __restrict__ out) {
    extern __shared__ float sm[];
    float* __restrict__ vs = sm;             // [TY][PW]  vertical 13-sums
    float* __restrict__ os = sm + TY * PW;   // [TY][OW]  warp-private staging

    const int ytile = blockIdx.x;
    const int plane = blockIdx.y;
    const int y0 = ytile * TY;
    const float* __restrict__ ip = in  + (size_t)plane * (Hd * Wd);
    float*       __restrict__ op = out + (size_t)plane * (Hd * Wd);
    const int t = threadIdx.x;               // 0..511
    const float k0 = kern[0];                // 1/169

    // ---- Pass 1: vertical running 13-sum, thread t = column t ----
    if (ytile >= 1 && ytile <= 30) {
        // interior: rows y0-6 .. y0+21 all in-bounds -> pure pointer walk
        const float* __restrict__ q = ip + (y0 - KHALF) * Wd + t;
        float s = 0.0f;
        #pragma unroll
        for (int j = 0; j < 12; j++)
            s += q[j * Wd];
        #pragma unroll
        for (int j = 0; j < TY; j++) {
            s += q[(j + 12) * Wd];                  // incoming row y0+j+6
            vs[j * PW + t] = s;
            s -= q[j * Wd];                         // outgoing row y0+j-6 (cache hit)
        }
    } else {
        // edge tiles: reflect indexing (unchanged from R12)
        float s = 0.0f;
        #pragma unroll
        for (int j = -KHALF; j < KHALF; j++)
            s += ip[reflect_i(y0 + j, Hd) * Wd + t];
        #pragma unroll
        for (int j = 0; j < TY; j++) {
            s += ip[reflect_i(y0 + j + KHALF, Hd) * Wd + t];
            vs[j * PW + t] = s;
            s -= ip[reflect_i(y0 + j - KHALF, Hd) * Wd + t];
        }
    }
    __syncthreads();   // the ONLY block-wide sync

    // ---- Pass 2 + flush: warp-private 32-column block, all 16 rows ----
    {
        const int lane = t & 31;
        const int w    = t >> 5;        // warp 0..15: columns [32w, 32w+32)
        const int rl   = lane & 15;     // row 0..15
        const int sc   = lane >> 4;     // half-block select
        const int xb   = 32 * w + 16 * sc;
        const float* __restrict__ vrow = vs + rl * PW;
        float* __restrict__ orow = os + rl * OW;

        if (w >= 1 && w <= 14) {
            // interior warps: x in [xb-6, xb+22] all in-bounds -> immediate offsets
            const float* __restrict__ vw = vrow + xb;
            float s = 0.0f;
            #pragma unroll
            for (int k = 0; k < 13; k++)
                s += vw[k - KHALF];
            #pragma unroll
            for (int i = 0; i < 16; i++) {
                orow[xb + i] = s * k0;  // STS banks (rl+16sc+i)%32: conflict-free
                s += vw[i + KHALF + 1] - vw[i - KHALF];
            }
        } else {
            // boundary warps 0 and 15: reflect (unchanged from R12)
            float s = 0.0f;
            #pragma unroll
            for (int k = 0; k < 13; k++)
                s += vrow[reflect_i(xb - KHALF + k, Wd)];
            #pragma unroll
            for (int i = 0; i < 16; i++) {
                orow[xb + i] = s * k0;
                s += vrow[reflect_i(xb + i + KHALF + 1, Wd)]
                   - vrow[reflect_i(xb + i - KHALF, Wd)];
            }
        }
        __syncwarp();

        // flush own 32-col block: lane = column -> 128B coalesced streaming STG
        const int c = 32 * w + lane;
        #pragma unroll
        for (int row = 0; row < TY; row++) {
            __stcs(&op[(size_t)(y0 + row) * Wd + c], os[row * OW + c]);
        }
    }
}

extern "C" void kernel_launch(void* const* d_in, const int* in_sizes, int n_in,
                              void* d_out, int out_size) {
    const float* input  = (const float*)d_in[0];   // (8,64,512,512) fp32
    const float* kernel = (const float*)d_in[1];   // (1,13,13) fp32 uniform
    float* out = (float*)d_out;

    cudaFuncSetAttribute(boxblur15, cudaFuncAttributeMaxDynamicSharedMemorySize,
                         SMEM_BYTES);

    dim3 grid(Hd / TY, 8 * 64);    // (32 y-tiles, 512 planes)
    boxblur15<<<grid, NT, SMEM_BYTES>>>(input, kernel, out);
}